// round 4
// baseline (speedup 1.0000x reference)
#include <cuda_runtime.h>

// PointPillarScatter: out[b,c,yi,xi] = feat[b,c,n*] where n* = max point index
// mapping to cell (yi,xi) in batch b (JAX scatter-set last-wins); 0 elsewhere.
// Index math replicates XLA: /0.16f -> *fp32(1/0.16f) == *6.25f exactly.
//
// Pipeline: init -> min(x,y) -> winner atomicMax
//   per batch b: transpose feat[b][c][n] -> row[b][n][64ch]   (256B rows)
//                fill: warp-cooperative 256B row gathers (2 wavefronts/cell)
//                      + SMEM transpose -> fully coalesced output stores.

namespace {
constexpr int B  = 4;
constexpr int C  = 64;
constexpr int N  = 100000;
constexpr int NY = 496;
constexpr int NX = 432;
constexpr int CELLS  = NY * NX;      // 214272 = 1674 * 128
constexpr int VCELLS = CELLS / 4;    // 53568
constexpr int TCELLS = 128;          // fill tile (cells per block)
constexpr int NTILE  = 32;           // transpose tile (points per block)
}

// Scratch (no runtime allocation allowed).
__device__ __align__(16) int   g_winner[B * CELLS];
__device__ float g_minxy[B][2];
__device__ __align__(16) float g_row[(size_t)B * N * C];   // 102.4 MB, [b][n][c]

__device__ __forceinline__ void atomicMinF(float* addr, float v) {
    if (v >= 0.0f) atomicMin((int*)addr, __float_as_int(v));
    else           atomicMax((unsigned int*)addr, __float_as_uint(v));
}

__global__ void pp_init() {
    int i = blockIdx.x * blockDim.x + threadIdx.x;
    if (i < B * VCELLS) reinterpret_cast<int4*>(g_winner)[i] = make_int4(-1, -1, -1, -1);
    if (i < B * 2) reinterpret_cast<float*>(g_minxy)[i] = __int_as_float(0x7f800000);
}

__global__ void pp_min(const float4* __restrict__ pts) {
    const int b = blockIdx.y;
    const float INF = __int_as_float(0x7f800000);
    float mx = INF, my = INF;
    for (int n = blockIdx.x * blockDim.x + threadIdx.x; n < N; n += gridDim.x * blockDim.x) {
        float4 v = pts[b * N + n];
        mx = fminf(mx, v.y);
        my = fminf(my, v.z);
    }
    #pragma unroll
    for (int o = 16; o; o >>= 1) {
        mx = fminf(mx, __shfl_xor_sync(0xffffffffu, mx, o));
        my = fminf(my, __shfl_xor_sync(0xffffffffu, my, o));
    }
    __shared__ float sx[32], sy[32];
    const int warp = threadIdx.x >> 5, lane = threadIdx.x & 31;
    if (lane == 0) { sx[warp] = mx; sy[warp] = my; }
    __syncthreads();
    if (warp == 0) {
        const int nw = blockDim.x >> 5;
        mx = (lane < nw) ? sx[lane] : INF;
        my = (lane < nw) ? sy[lane] : INF;
        #pragma unroll
        for (int o = 16; o; o >>= 1) {
            mx = fminf(mx, __shfl_xor_sync(0xffffffffu, mx, o));
            my = fminf(my, __shfl_xor_sync(0xffffffffu, my, o));
        }
        if (lane == 0) {
            atomicMinF(&g_minxy[b][0], mx);
            atomicMinF(&g_minxy[b][1], my);
        }
    }
}

__global__ void pp_winner(const float4* __restrict__ pts) {
    const int b = blockIdx.y;
    const float xmin = g_minxy[b][0];
    const float ymin = g_minxy[b][1];
    const int n = blockIdx.x * blockDim.x + threadIdx.x;
    if (n >= N) return;
    float4 v = pts[b * N + n];
    const float R = 6.25f;                 // fp32(1/0.16f) == 6.25f (XLA rewrite)
    int xi = (int)floorf((v.y - xmin) * R);
    int yi = (int)floorf((v.z - ymin) * R);
    xi = min(max(xi, 0), NX - 1);
    yi = min(max(yi, 0), NY - 1);
    atomicMax(&g_winner[b * CELLS + yi * NX + xi], n);
}

// SMEM-tiled transpose: feat[b][c][n0..n0+31] -> row[b][n][c] (256B rows).
// Both global sides fully coalesced. XOR swizzle keyed on n keeps SMEM clean.
__global__ void __launch_bounds__(256) pp_transpose64(const float* __restrict__ feat, int b) {
    __shared__ float S[NTILE * C];   // 8 KB
    const int n0 = blockIdx.x * NTILE;
    const float4* fin = reinterpret_cast<const float4*>(feat) + (size_t)b * C * (N / 4);
    #pragma unroll
    for (int it = 0; it < 2; ++it) {
        int idx = it * 256 + threadIdx.x;          // 512 float4 reads
        int c  = idx >> 3;                         // 0..63
        int nf = idx & 7;                          // float4 within 32 points
        float4 v = fin[(size_t)c * (N / 4) + (n0 >> 2) + nf];
        int n = nf * 4;
        int hi = c >> 2, lo = c & 3;
        S[(n + 0) * C + (((hi) ^ ((n + 0) & 15)) << 2) + lo] = v.x;
        S[(n + 1) * C + (((hi) ^ ((n + 1) & 15)) << 2) + lo] = v.y;
        S[(n + 2) * C + (((hi) ^ ((n + 2) & 15)) << 2) + lo] = v.z;
        S[(n + 3) * C + (((hi) ^ ((n + 3) & 15)) << 2) + lo] = v.w;
    }
    __syncthreads();
    float4* ro = reinterpret_cast<float4*>(g_row) + ((size_t)b * N + n0) * 16;
    const float4* Sf4 = reinterpret_cast<const float4*>(S);
    #pragma unroll
    for (int it = 0; it < 2; ++it) {
        int idx = it * 256 + threadIdx.x;          // 512 float4 writes
        int n = idx >> 4, cf4 = idx & 15;
        ro[n * 16 + cf4] = Sf4[n * 16 + (cf4 ^ (n & 15))];
    }
}

// Fill: block = 128 cells of batch b, all 64 channels.
// Phase A: warp-cooperative gather — 16 lanes fetch one cell's 256B row
//          (2 L1 wavefronts/cell) into swizzled SMEM.
// Phase B: coalesced stores — float4 = 4 consecutive cells per channel.
__global__ void __launch_bounds__(256) pp_fill64(float4* __restrict__ out, int b) {
    __shared__ float S[TCELLS * C];   // 32 KB
    __shared__ int   w_s[TCELLS];
    const int base = blockIdx.x * TCELLS;
    const int t = threadIdx.x;
    if (t < TCELLS) w_s[t] = g_winner[b * CELLS + base + t];
    __syncthreads();

    const float4* rp = reinterpret_cast<const float4*>(g_row) + (size_t)b * N * 16;
    const float4 z = make_float4(0.f, 0.f, 0.f, 0.f);
    const int chunk = t & 15;
    #pragma unroll
    for (int it = 0; it < TCELLS / 16; ++it) {     // 8 iters
        int cl = (t >> 4) + it * 16;
        int n = w_s[cl];
        float4 v = (n >= 0) ? __ldg(rp + (size_t)n * 16 + chunk) : z;
        reinterpret_cast<float4*>(S)[cl * 16 + (chunk ^ ((cl >> 2) & 15))] = v;
    }
    __syncthreads();

    const int m  = t & 31;                         // float4-of-cells index (4m..4m+3)
    const int c0 = t >> 5;                         // 0..7
    const int key = m & 15;
    float4* ob = out + (size_t)b * C * VCELLS + (base >> 2) + m;
    #pragma unroll
    for (int c = 0; c < C / 8; ++c) {              // 8 channel iters
        int ch = c0 + c * 8;
        int swz = (((ch >> 2) ^ key) << 2) + (ch & 3);
        float4 o;
        o.x = S[(4 * m + 0) * C + swz];
        o.y = S[(4 * m + 1) * C + swz];
        o.z = S[(4 * m + 2) * C + swz];
        o.w = S[(4 * m + 3) * C + swz];
        ob[(size_t)ch * VCELLS] = o;
    }
}

extern "C" void kernel_launch(void* const* d_in, const int* in_sizes, int n_in,
                              void* d_out, int out_size) {
    (void)in_sizes; (void)n_in; (void)out_size;
    const float*  feat = (const float*)d_in[0];   // (B, C, N) f32
    const float4* pts  = (const float4*)d_in[1];  // (B*N, 4)  f32
    // d_in[2] (voxel_coords) unused by the reference computation.

    pp_init<<<(B * VCELLS + 255) / 256, 256>>>();
    pp_min<<<dim3(98, B), 256>>>(pts);
    pp_winner<<<dim3((N + 255) / 256, B), 256>>>(pts);
    // Per-batch transpose/fill pairs: the 25.6 MB interleaved slice stays
    // L2-resident between the pair, so fill's gathers hit L2.
    for (int b = 0; b < B; ++b) {
        pp_transpose64<<<N / NTILE, 256>>>(feat, b);
        pp_fill64<<<CELLS / TCELLS, 256>>>((float4*)d_out, b);
    }
}